// round 2
// baseline (speedup 1.0000x reference)
#include <cuda_runtime.h>
#include <math_constants.h>

#define BB 32
#define NN 784
#define CC 256
#define FF 1024
#define MM (BB*NN)      // 25088
#define HEADS 8
#define DIMH 32

typedef unsigned long long u64;

// ---- f32x2 packed-math helpers (Blackwell FFMA2 path) ----
__device__ __forceinline__ u64 pk2(float lo, float hi) {
    u64 r; asm("mov.b64 %0,{%1,%2};" : "=l"(r) : "f"(lo), "f"(hi)); return r;
}
__device__ __forceinline__ void upk2(u64 v, float& lo, float& hi) {
    asm("mov.b64 {%0,%1},%2;" : "=f"(lo), "=f"(hi) : "l"(v));
}
__device__ __forceinline__ void fma2(u64& d, u64 a, u64 b) {
    asm("fma.rn.f32x2 %0,%1,%2,%3;" : "=l"(d) : "l"(a), "l"(b), "l"(d));
}
__device__ __forceinline__ void mul2(u64& d, u64 a) {
    asm("mul.rn.f32x2 %0,%1,%2;" : "=l"(d) : "l"(d), "l"(a));
}

// ---------------- scratch (static device globals; no allocation) ----------------
__device__ float g_x[(size_t)MM * FF];       // QKV projection output [25088,1024]
__device__ float g_attn[(size_t)MM * 512];   // attention output [25088,512]
__device__ float g_sum[FF];
__device__ float g_sumsq[FF];
__device__ float g_affa[FF];                 // rstd*scale
__device__ float g_affb[FF];                 // -mean*rstd*scale

// ---------------- zero BN accumulators ----------------
__global__ void zero_stats_kernel() {
    int i = blockIdx.x * blockDim.x + threadIdx.x;
    if (i < FF) { g_sum[i] = 0.f; g_sumsq[i] = 0.f; }
}

// ---------------- SGEMM: C[M,N] = A[M,K]*B[K,N], 128x64 block, 8x4 micro, f32x2 ----------------
// As: [128][32] row-major (reads broadcast over ty). Bs_t: [64][32] = B transposed with
// 3-bit XOR swizzle on the float4 group so reads across tx are bank-conflict-free.
template<int KTOT, int LDA, int LDB, int LDC, bool STATS>
__global__ __launch_bounds__(256, 2) void sgemm_kernel(
    const float* __restrict__ A, const float* __restrict__ Bm, float* __restrict__ C)
{
    __shared__ __align__(16) float As[128 * 32];
    __shared__ __align__(16) float Bst[64 * 32];
    __shared__ float csum[64], csq[64];

    const int m0 = blockIdx.y * 128;
    const int n0 = blockIdx.x * 64;
    const int tid = threadIdx.x;
    const int tx = tid & 15, ty = tid >> 4;
    const int tx4 = tx * 4;

    u64 acc2[8][4] = {};   // packed (even-k, odd-k) partial sums

    for (int k0 = 0; k0 < KTOT; k0 += 32) {
        // A tile 128x32: 1024 float4, 4 per thread, plain row-major
        #pragma unroll
        for (int r = 0; r < 4; r++) {
            int f4 = tid + r * 256;
            int m = f4 >> 3, kq = f4 & 7;
            float4 v = *reinterpret_cast<const float4*>(&A[(size_t)(m0 + m) * LDA + k0 + kq * 4]);
            *reinterpret_cast<float4*>(&As[m * 32 + kq * 4]) = v;
        }
        // B tile 32x64 -> transposed Bst[n][k] with swizzle, scalar scatter stores
        #pragma unroll
        for (int r = 0; r < 2; r++) {
            int f4 = tid + r * 256;
            int k = f4 >> 4, n4 = f4 & 15;
            float4 v = *reinterpret_cast<const float4*>(&Bm[(size_t)(k0 + k) * LDB + n0 + n4 * 4]);
            float vs[4] = {v.x, v.y, v.z, v.w};
            #pragma unroll
            for (int s = 0; s < 4; s++) {
                int n = n4 * 4 + s;
                Bst[n * 32 + ((((k >> 2) ^ ((n >> 2) & 7)) << 2) | (k & 3))] = vs[s];
            }
        }
        __syncthreads();
        #pragma unroll
        for (int dq = 0; dq < 8; dq++) {
            ulonglong2 b2[4];
            #pragma unroll
            for (int j = 0; j < 4; j++)
                b2[j] = *reinterpret_cast<const ulonglong2*>(
                    &Bst[(tx4 + j) * 32 + ((dq ^ (tx & 7)) << 2)]);
            #pragma unroll
            for (int i = 0; i < 8; i++) {
                ulonglong2 a2 = *reinterpret_cast<const ulonglong2*>(
                    &As[(ty * 8 + i) * 32 + dq * 4]);
                #pragma unroll
                for (int j = 0; j < 4; j++) {
                    fma2(acc2[i][j], a2.x, b2[j].x);
                    fma2(acc2[i][j], a2.y, b2[j].y);
                }
            }
        }
        __syncthreads();
    }

    float accf[8][4];
    #pragma unroll
    for (int i = 0; i < 8; i++)
        #pragma unroll
        for (int j = 0; j < 4; j++) {
            float lo, hi; upk2(acc2[i][j], lo, hi);
            accf[i][j] = lo + hi;
        }

    #pragma unroll
    for (int i = 0; i < 8; i++) {
        float4 o = make_float4(accf[i][0], accf[i][1], accf[i][2], accf[i][3]);
        *reinterpret_cast<float4*>(&C[(size_t)(m0 + ty * 8 + i) * LDC + n0 + tx4]) = o;
    }

    if (STATS) {
        if (tid < 64) { csum[tid] = 0.f; csq[tid] = 0.f; }
        __syncthreads();
        #pragma unroll
        for (int j = 0; j < 4; j++) {
            float s = 0.f, sq = 0.f;
            #pragma unroll
            for (int i = 0; i < 8; i++) { float v = accf[i][j]; s += v; sq = fmaf(v, v, sq); }
            atomicAdd(&csum[tx4 + j], s);
            atomicAdd(&csq[tx4 + j], sq);
        }
        __syncthreads();
        if (tid < 64) {
            atomicAdd(&g_sum[n0 + tid], csum[tid]);
            atomicAdd(&g_sumsq[n0 + tid], csq[tid]);
        }
    }
}

// ---------------- BN finalize: affine a,b per feature ----------------
__global__ void bn_finalize_kernel(const float* __restrict__ bn_scale) {
    int f = blockIdx.x * blockDim.x + threadIdx.x;
    if (f < FF) {
        float mean = g_sum[f] * (1.f / MM);
        float var  = g_sumsq[f] * (1.f / MM) - mean * mean;
        float r = rsqrtf(var + 1e-5f);
        float a = r * bn_scale[f];
        g_affa[f] = a;
        g_affb[f] = -mean * a;
    }
}

// ---------------- fused flash attention: QT=56, KT=64, 224 threads, f32x2 ----------------
// Qs: [q][32] plain (reads broadcast over ty).
// Ks: [k][32] with 3-bit XOR swizzle on float4 group -> conflict-free reads across tx.
// Vt: [vd][k] transposed + swizzled -> conflict-free reads across tx.
// Ss: [q][64] plain (writes/reads across tx4 conflict-free; P reads broadcast over ty).
__global__ __launch_bounds__(224) void attention_kernel(
    const float* __restrict__ bias, float* __restrict__ out)
{
    __shared__ __align__(16) float Qs[56 * 32];
    __shared__ __align__(16) float Ks[64 * 32];
    __shared__ __align__(16) float Vt[64 * 64];
    __shared__ __align__(16) float Ss[56 * 64];
    __shared__ float cA[128], cB[128];
    __shared__ float m_s[56], l_s[56], alpha_s[56];

    const int tid = threadIdx.x;
    const int tx = tid & 15, ty = tid >> 4;       // ty 0..13
    const int tx4 = tx * 4, ty4 = ty * 4;
    const int q0 = blockIdx.x * 56;
    const int h  = blockIdx.y;
    const int b  = blockIdx.z;

    // normalization coefficients for the 4 feature segments this head uses
    if (tid < 128) {
        int seg = tid >> 5, d = tid & 31;
        int f = seg * 256 + h * 32 + d;
        cA[tid] = g_affa[f];
        cB[tid] = g_affb[f];
    }
    if (tid < 56) { m_s[tid] = -CUDART_INF_F; l_s[tid] = 0.f; }
    __syncthreads();

    // Q tile [56,32], normalized (plain layout, conflict-free stores)
    for (int idx = tid; idx < 56 * 32; idx += 224) {
        int q = idx >> 5, d = idx & 31;
        float v = g_x[(size_t)(b * NN + q0 + q) * FF + h * 32 + d];
        Qs[q * 32 + d] = fmaf(v, cA[d], cB[d]);
    }

    u64 acc2[4][4] = {};   // packed (even-k, odd-k) PV partial sums

    for (int kc = 0; kc < 13; kc++) {
        const int k0 = kc * 64;
        __syncthreads();  // protect Ks/Vt/Ss from previous-iteration consumers

        // K chunk [64,32] swizzled
        for (int idx = tid; idx < 64 * 32; idx += 224) {
            int k = idx >> 5, d = idx & 31;
            int row = k0 + k;
            float v = (row < NN) ? fmaf(g_x[(size_t)(b * NN + row) * FF + 256 + h * 32 + d],
                                        cA[32 + d], cB[32 + d]) : 0.f;
            Ks[k * 32 + ((((d >> 2) ^ ((k >> 2) & 7)) << 2) | (d & 3))] = v;
        }
        // V chunk -> transposed Vt[vd][k], swizzled
        for (int idx = tid; idx < 64 * 64; idx += 224) {
            int k = idx >> 6, vd = idx & 63;
            int row = k0 + k;
            int col = 512 + ((vd >> 5) << 8) + h * 32 + (vd & 31);
            float v = (row < NN) ? fmaf(g_x[(size_t)(b * NN + row) * FF + col],
                                        cA[64 + vd], cB[64 + vd]) : 0.f;
            Vt[vd * 64 + ((((k >> 2) ^ ((vd >> 2) & 7)) << 2) | (k & 3))] = v;
        }
        __syncthreads();

        // S = Q K^T, packed along d
        {
            u64 s2[4][4] = {};
            #pragma unroll
            for (int dq = 0; dq < 8; dq++) {
                ulonglong2 kb[4];
                #pragma unroll
                for (int j = 0; j < 4; j++)
                    kb[j] = *reinterpret_cast<const ulonglong2*>(
                        &Ks[(tx4 + j) * 32 + ((dq ^ (tx & 7)) << 2)]);
                #pragma unroll
                for (int i = 0; i < 4; i++) {
                    ulonglong2 qa = *reinterpret_cast<const ulonglong2*>(
                        &Qs[(ty4 + i) * 32 + dq * 4]);
                    #pragma unroll
                    for (int j = 0; j < 4; j++) {
                        fma2(s2[i][j], qa.x, kb[j].x);
                        fma2(s2[i][j], qa.y, kb[j].y);
                    }
                }
            }
            if (k0 + tx4 < NN) {   // 784 % 4 == 0 -> whole float4 valid or invalid
                #pragma unroll
                for (int i = 0; i < 4; i++) {
                    float4 bi = *reinterpret_cast<const float4*>(
                        &bias[(size_t)(q0 + ty4 + i) * NN + k0 + tx4]);
                    float v[4];
                    #pragma unroll
                    for (int j = 0; j < 4; j++) {
                        float lo, hi; upk2(s2[i][j], lo, hi);
                        v[j] = lo + hi;
                    }
                    *reinterpret_cast<float4*>(&Ss[(ty4 + i) * 64 + tx4]) =
                        make_float4(v[0] + bi.x, v[1] + bi.y, v[2] + bi.z, v[3] + bi.w);
                }
            } else {
                #pragma unroll
                for (int i = 0; i < 4; i++)
                    *reinterpret_cast<float4*>(&Ss[(ty4 + i) * 64 + tx4]) =
                        make_float4(-1e30f, -1e30f, -1e30f, -1e30f);
            }
        }
        __syncthreads();

        // online softmax: 4 threads per row, contiguous 16-wide segments
        {
            int r = tid >> 2, sub = tid & 3;
            float* row = &Ss[r * 64 + sub * 16];
            float mx = -CUDART_INF_F;
            #pragma unroll
            for (int it = 0; it < 16; it++) mx = fmaxf(mx, row[it]);
            mx = fmaxf(mx, __shfl_xor_sync(0xffffffffu, mx, 1));
            mx = fmaxf(mx, __shfl_xor_sync(0xffffffffu, mx, 2));
            float mold = m_s[r];
            float mnew = fmaxf(mold, mx);
            float sum = 0.f;
            #pragma unroll
            for (int it = 0; it < 16; it++) {
                float p = __expf(row[it] - mnew);
                row[it] = p;
                sum += p;
            }
            sum += __shfl_xor_sync(0xffffffffu, sum, 1);
            sum += __shfl_xor_sync(0xffffffffu, sum, 2);
            if (sub == 0) {
                float al = __expf(mold - mnew);
                alpha_s[r] = al;
                l_s[r] = fmaf(l_s[r], al, sum);
                m_s[r] = mnew;
            }
        }
        __syncthreads();

        // rescale + PV accumulate (packed along k)
        #pragma unroll
        for (int i = 0; i < 4; i++) {
            u64 al2 = pk2(alpha_s[ty4 + i], alpha_s[ty4 + i]);
            #pragma unroll
            for (int j = 0; j < 4; j++) mul2(acc2[i][j], al2);
        }
        #pragma unroll
        for (int kk = 0; kk < 16; kk++) {
            ulonglong2 Vv[4];
            #pragma unroll
            for (int j = 0; j < 4; j++)
                Vv[j] = *reinterpret_cast<const ulonglong2*>(
                    &Vt[(tx4 + j) * 64 + ((kk ^ (tx & 7)) << 2)]);
            #pragma unroll
            for (int i = 0; i < 4; i++) {
                ulonglong2 P = *reinterpret_cast<const ulonglong2*>(
                    &Ss[(ty4 + i) * 64 + kk * 4]);
                #pragma unroll
                for (int j = 0; j < 4; j++) {
                    fma2(acc2[i][j], P.x, Vv[j].x);
                    fma2(acc2[i][j], P.y, Vv[j].y);
                }
            }
        }
    }

    // epilogue: fold pairs, /l, hard_swish, write [ (b*N+q), h*64 + vd ]
    #pragma unroll
    for (int i = 0; i < 4; i++) {
        int q = ty4 + i;
        float inv = 1.0f / l_s[q];
        float o[4];
        #pragma unroll
        for (int j = 0; j < 4; j++) {
            float lo, hi; upk2(acc2[i][j], lo, hi);
            float v = (lo + hi) * inv;
            o[j] = v * __saturatef((v + 3.0f) * (1.0f / 6.0f));
        }
        *reinterpret_cast<float4*>(&out[((size_t)(b * NN + q0 + q)) * 512 + h * 64 + tx4]) =
            make_float4(o[0], o[1], o[2], o[3]);
    }
}

// ---------------- launch ----------------
extern "C" void kernel_launch(void* const* d_in, const int* in_sizes, int n_in,
                              void* d_out, int out_size) {
    const float* inputs    = (const float*)d_in[0];
    const float* w_qkv     = (const float*)d_in[1];
    const float* bn_scale  = (const float*)d_in[2];
    const float* attn_bias = (const float*)d_in[3];
    const float* w_out     = (const float*)d_in[4];
    float* out = (float*)d_out;

    float *px, *pattn;
    cudaGetSymbolAddress((void**)&px, g_x);
    cudaGetSymbolAddress((void**)&pattn, g_attn);

    zero_stats_kernel<<<4, 256>>>();
    // x = inputs @ w_qkv, fused per-feature sum/sumsq
    sgemm_kernel<256, 256, 1024, 1024, true><<<dim3(16, 196), 256>>>(inputs, w_qkv, px);
    bn_finalize_kernel<<<4, 256>>>(bn_scale);
    // fused BN-normalize + flash attention + hard_swish
    attention_kernel<<<dim3(14, HEADS, BB), 224>>>(attn_bias, pattn);
    // final projection
    sgemm_kernel<512, 512, 256, 256, false><<<dim3(4, 196), 256>>>(pattn, w_out, out);
}